// round 15
// baseline (speedup 1.0000x reference)
#include <cuda_runtime.h>
#include <cuda_fp16.h>
#include <math.h>
#include <stdint.h>

// ---------------- problem constants ----------------
#define BB   2
#define TT   2048
#define NL   2
#define NH   12
#define ED   768
#define HDD  64
#define FFD  3072
#define VV   50257
#define NTOK (BB*TT)      // 4096
#define E3   (3*ED)       // 2304
#define NBLK_MAX ((VV + 127) / 128)       // 393 (stat buffer sizing)
#define NBLK_LOG ((VV + 255) / 256)       // 197 (logits 256-col blocks)

// ---------------- scratch (device globals: allocation-free) ----------------
__device__ float  g_x   [NTOK*ED];          // fp32 residual stream
__device__ __half g_h   [NTOK*ED];          // LN output (GEMM A input)
__device__ __half g_qkv [NTOK*E3];
__device__ __half g_y   [NTOK*ED];
__device__ __half g_ff  [NTOK*FFD];
__device__ float  g_nll [NTOK];
__device__ float  g_stat_m[(size_t)NTOK*NBLK_MAX];
__device__ float  g_stat_s[(size_t)NTOK*NBLK_MAX];
__device__ float  g_logits_scratch[(size_t)NTOK*VV];
// fp16 transposed weights Bt[N,K] + fp16 wte
__device__ __half g_attn_wT[NL*E3*ED];
__device__ __half g_proj_wT[NL*ED*ED];
__device__ __half g_fc1_wT [NL*FFD*ED];
__device__ __half g_fc2_wT [NL*ED*FFD];
__device__ __half g_wte_h  [(size_t)VV*ED];

// ---------------- helpers ----------------
__device__ __forceinline__ uint32_t smem_u32(const void* p) {
    uint32_t a;
    asm("{ .reg .u64 t; cvta.to.shared.u64 t, %1; cvt.u32.u64 %0, t; }" : "=r"(a) : "l"(p));
    return a;
}
#define CP16(sm, gp) \
    asm volatile("cp.async.cg.shared.global [%0], [%1], 16;" :: "r"(sm), "l"(gp) : "memory")
#define CP16Z(sm, gp) \
    asm volatile("cp.async.ca.shared.global [%0], [%1], 16, 0;" :: "r"(sm), "l"(gp) : "memory")
#define CP_COMMIT() asm volatile("cp.async.commit_group;" ::: "memory")
#define CP_WAIT(n)  asm volatile("cp.async.wait_group %0;" :: "n"(n) : "memory")

__device__ __forceinline__ void ldsm4(uint32_t r[4], uint32_t addr) {
    asm volatile("ldmatrix.sync.aligned.m8n8.x4.shared.b16 {%0,%1,%2,%3}, [%4];"
                 : "=r"(r[0]), "=r"(r[1]), "=r"(r[2]), "=r"(r[3]) : "r"(addr));
}
__device__ __forceinline__ void ldsm4t(uint32_t r[4], uint32_t addr) {
    asm volatile("ldmatrix.sync.aligned.m8n8.x4.trans.shared.b16 {%0,%1,%2,%3}, [%4];"
                 : "=r"(r[0]), "=r"(r[1]), "=r"(r[2]), "=r"(r[3]) : "r"(addr));
}
__device__ __forceinline__ void mma_f16(float c[4], const uint32_t a[4],
                                        uint32_t b0, uint32_t b1) {
    asm volatile("mma.sync.aligned.m16n8k16.row.col.f32.f16.f16.f32 "
                 "{%0,%1,%2,%3}, {%4,%5,%6,%7}, {%8,%9}, {%0,%1,%2,%3};"
                 : "+f"(c[0]), "+f"(c[1]), "+f"(c[2]), "+f"(c[3])
                 : "r"(a[0]), "r"(a[1]), "r"(a[2]), "r"(a[3]), "r"(b0), "r"(b1));
}
__device__ __forceinline__ uint32_t packh2(float x, float y) {
    __half2 h = __floats2half2_rn(x, y);
    return *(uint32_t*)&h;
}

// ---------------- embedding ----------------
__global__ void embed_k(const int* __restrict__ idx, const float* __restrict__ wte,
                        const float* __restrict__ wpe, float* __restrict__ x) {
    int i = blockIdx.x * blockDim.x + threadIdx.x;
    if (i < NTOK * ED) {
        int tok = i / ED, e = i - tok * ED;
        int t = tok % TT;
        x[i] = wte[(size_t)idx[tok] * ED + e] + wpe[(size_t)t * ED + e];
    }
}

// ---------------- layernorm (fp32 in -> fp16 out) ----------------
__global__ void ln_k(const float* __restrict__ x, const float* __restrict__ g,
                     const float* __restrict__ b, __half* __restrict__ o) {
    int row = blockIdx.x;
    int t = threadIdx.x;
    const float* xr = x + (size_t)row * ED;
    float v0 = xr[t], v1 = xr[t + 256], v2 = xr[t + 512];
    float s1 = v0 + v1 + v2;
    float s2 = v0 * v0 + v1 * v1 + v2 * v2;
    __shared__ float r1[256], r2[256];
    r1[t] = s1; r2[t] = s2;
    __syncthreads();
    for (int s = 128; s > 0; s >>= 1) {
        if (t < s) { r1[t] += r1[t + s]; r2[t] += r2[t + s]; }
        __syncthreads();
    }
    float mu  = r1[0] * (1.0f / ED);
    float var = r2[0] * (1.0f / ED) - mu * mu;
    float inv = rsqrtf(var + 1e-5f);
    __half* orow = o + (size_t)row * ED;
    orow[t]       = __float2half((v0 - mu) * inv * g[t]       + b[t]);
    orow[t + 256] = __float2half((v1 - mu) * inv * g[t + 256] + b[t + 256]);
    orow[t + 512] = __float2half((v2 - mu) * inv * g[t + 512] + b[t + 512]);
}

// ---------------- fused weight prep: 8 transposes + wte cvt in ONE launch ----------------
#define T_ATTN 1728
#define T_PROJ 576
#define T_FC1  2304
#define T_FC2  2304
#define T_LAYER (T_ATTN + T_PROJ + T_FC1 + T_FC2)   // 6912
#define T_ALL   (NL * T_LAYER)                      // 13824
#define WTE_EL  ((size_t)VV * ED)                   // 38597376
#define CVT_PB  2048
#define CVT_BLKS ((int)((WTE_EL + CVT_PB - 1) / CVT_PB))

__device__ __forceinline__ void tr_tile(const float* __restrict__ in, __half* __restrict__ out,
                                        int K, int N, int tk, int tn,
                                        int tx, int ty, float (*t)[33]) {
    int n0 = tn * 32, k0 = tk * 32;
    #pragma unroll
    for (int i = ty; i < 32; i += 8)
        t[i][tx] = in[(size_t)(k0 + i) * N + n0 + tx];
    __syncthreads();
    #pragma unroll
    for (int i = ty; i < 32; i += 8)
        out[(size_t)(n0 + i) * K + k0 + tx] = __float2half(t[tx][i]);
}

__global__ __launch_bounds__(256)
void prep_k(const float* __restrict__ attn_w, const float* __restrict__ proj_w,
            const float* __restrict__ fc1_w,  const float* __restrict__ fc2_w,
            const float* __restrict__ wte,
            __half* __restrict__ attn_wT, __half* __restrict__ proj_wT,
            __half* __restrict__ fc1_wT,  __half* __restrict__ fc2_wT,
            __half* __restrict__ wte_h) {
    int b = blockIdx.x;
    if (b < T_ALL) {
        __shared__ float t[32][33];
        int tx = threadIdx.x & 31, ty = threadIdx.x >> 5;
        int layer = b / T_LAYER;
        int r = b - layer * T_LAYER;
        if (r < T_ATTN) {
            tr_tile(attn_w + (size_t)layer * ED * E3, attn_wT + (size_t)layer * E3 * ED,
                    ED, E3, r / (E3 / 32), r % (E3 / 32), tx, ty, t);
        } else if ((r -= T_ATTN) < T_PROJ) {
            tr_tile(proj_w + (size_t)layer * ED * ED, proj_wT + (size_t)layer * ED * ED,
                    ED, ED, r / (ED / 32), r % (ED / 32), tx, ty, t);
        } else if ((r -= T_PROJ) < T_FC1) {
            tr_tile(fc1_w + (size_t)layer * ED * FFD, fc1_wT + (size_t)layer * FFD * ED,
                    ED, FFD, r / (FFD / 32), r % (FFD / 32), tx, ty, t);
        } else {
            r -= T_FC1;
            tr_tile(fc2_w + (size_t)layer * FFD * ED, fc2_wT + (size_t)layer * ED * FFD,
                    FFD, ED, r / (ED / 32), r % (ED / 32), tx, ty, t);
        }
    } else {
        size_t base = (size_t)(b - T_ALL) * CVT_PB + (size_t)threadIdx.x * 8;
        if (base + 8 <= WTE_EL) {
            float4 v0 = *(const float4*)(wte + base);
            float4 v1 = *(const float4*)(wte + base + 4);
            __half2 h0 = __floats2half2_rn(v0.x, v0.y);
            __half2 h1 = __floats2half2_rn(v0.z, v0.w);
            __half2 h2 = __floats2half2_rn(v1.x, v1.y);
            __half2 h3 = __floats2half2_rn(v1.z, v1.w);
            uint2 o0 = make_uint2(*(uint32_t*)&h0, *(uint32_t*)&h1);
            uint2 o1 = make_uint2(*(uint32_t*)&h2, *(uint32_t*)&h3);
            *(uint2*)(wte_h + base)     = o0;
            *(uint2*)(wte_h + base + 4) = o1;
        } else {
            for (size_t i = base; i < WTE_EL; i++)
                wte_h[i] = __float2half(wte[i]);
        }
    }
}

// ---------------- fp16 mma.sync GEMM: C[M,N] = A[M,K] @ Bt[N,K]^T ----------------
// Block tile 128 x (NWN*32), 64*NWN threads = 2*NWN warps (2M x NWN-N),
// warp tile 64x32. BK=64, 3-stage cp.async pipeline, one sync/iter.
// NWN=4: 128x128, 256 thr (layer GEMMs). NWN=8: 128x256, 512 thr (logits).
#define RSH    72
#define NST    3

template<int NWN, bool BIAS, bool GELU, bool RES, bool OUTH, bool STATS>
__global__ __launch_bounds__(64 * NWN)
void gemm_h(int M, int N, int K,
            const __half* __restrict__ A, const __half* __restrict__ B,
            const float* __restrict__ bias, const float* __restrict__ res,
            void* __restrict__ Cv,
            float* __restrict__ stm, float* __restrict__ sts, int nblk) {
    constexpr int THREADS = 64 * NWN;
    constexpr int BN      = NWN * 32;
    constexpr int A_TB    = 128 * RSH * 2;
    constexpr int B_TB    = BN  * RSH * 2;
    constexpr int STGB    = A_TB + B_TB;
    constexpr int JOBS    = (128 + BN) * 8 / THREADS;   // cp.async chunks per thread

    extern __shared__ char sm[];
    uint32_t sbase = smem_u32(sm);

    int tid = threadIdx.x;
    int wid = tid >> 5;
    int lid = tid & 31;
    int g = lid >> 2;          // 0..7
    int t4 = lid & 3;          // 0..3
    int wm = wid & 1;          // M warp (0..1) -> 64 rows
    int wn = wid >> 1;         // N warp (0..NWN-1) -> 32 cols
    int bm = blockIdx.x * 128;
    int bn = blockIdx.y * BN;

    int mat = lid >> 3, r8 = lid & 7;
    int a_row  = wm * 64 + ((mat & 1) << 3) + r8;
    int a_colb = ((mat >> 1) << 3) * 2;
    int b_row  = wn * 32 + ((mat >> 1) << 3) + r8;
    int b_colb = ((mat & 1) << 3) * 2;

    float cfr[4][4][4];
    #pragma unroll
    for (int f = 0; f < 4; f++)
        #pragma unroll
        for (int j = 0; j < 4; j++)
            #pragma unroll
            for (int c = 0; c < 4; c++) cfr[f][j][c] = 0.f;

    const int KT = K >> 6;     // 64-K tiles

    auto load_tile = [&](int kt, int stage) {
        int k0 = kt << 6;
        uint32_t st = sbase + (uint32_t)stage * STGB;
        #pragma unroll
        for (int i = 0; i < JOBS; i++) {
            int lin = i * THREADS + tid;
            int r = lin >> 3;          // 0..(128+BN-1)
            int c = lin & 7;           // 16B chunk (8 per row)
            if (r < 128) {
                const __half* gpa = A + (size_t)(bm + r) * K + k0 + c * 8;
                CP16(st + (uint32_t)r * (RSH * 2) + (uint32_t)c * 16, gpa);
            } else {
                int rb = r - 128;
                int n = bn + rb;
                uint32_t smb = st + (uint32_t)A_TB + (uint32_t)rb * (RSH * 2) + (uint32_t)c * 16;
                const __half* gpb = B + (size_t)n * K + k0 + c * 8;
                if (n < N) CP16(smb, gpb);
                else       CP16Z(smb, B);
            }
        }
    };

    auto compute = [&](int stage) {
        uint32_t stA = sbase + (uint32_t)stage * STGB;
        uint32_t aBase = stA + (uint32_t)a_row * (RSH * 2) + (uint32_t)a_colb;
        uint32_t bBase = stA + A_TB + (uint32_t)b_row * (RSH * 2) + (uint32_t)b_colb;
        #pragma unroll
        for (int s = 0; s < 4; s++) {
            uint32_t a[4][4], b[2][4];
            #pragma unroll
            for (int f = 0; f < 4; f++)
                ldsm4(a[f], aBase + s * 32 + f * (16 * RSH * 2));
            #pragma unroll
            for (int p = 0; p < 2; p++)
                ldsm4(b[p], bBase + s * 32 + p * (16 * RSH * 2));
            #pragma unroll
            for (int f = 0; f < 4; f++)
                #pragma unroll
                for (int j = 0; j < 4; j++)
                    mma_f16(cfr[f][j], a[f], b[j >> 1][(j & 1) * 2], b[j >> 1][(j & 1) * 2 + 1]);
        }
    };

    // one-sync-per-iteration 3-stage pipeline, prefetch distance 2 (x64 K).
    load_tile(0, 0); CP_COMMIT();
    if (KT > 1) { load_tile(1, 1); CP_COMMIT(); }
    for (int kt = 0; kt < KT; kt++) {
        if (kt + 1 < KT) CP_WAIT(1);
        else             CP_WAIT(0);
        __syncthreads();
        if (kt + 2 < KT) { load_tile(kt + 2, (kt + 2) % NST); CP_COMMIT(); }
        compute(kt % NST);
    }

    // ---- write C (scalar fp32 stores: N may be odd -> no STG.64) ----
    #pragma unroll
    for (int f = 0; f < 4; f++) {
        #pragma unroll
        for (int j = 0; j < 4; j++) {
            int m0 = bm + wm * 64 + f * 16 + g;
            int n0 = bn + wn * 32 + j * 8 + t4 * 2;
            #pragma unroll
            for (int half = 0; half < 2; half++) {
                int m = m0 + half * 8;
                float v0 = cfr[f][j][half * 2];
                float v1 = cfr[f][j][half * 2 + 1];
                if (BIAS) { v0 += bias[n0]; v1 += bias[n0 + 1]; }
                if (GELU) {
                    v0 = 0.5f * v0 * (1.f + erff(v0 * 0.70710678118654752f));
                    v1 = 0.5f * v1 * (1.f + erff(v1 * 0.70710678118654752f));
                }
                if (RES) {
                    v0 += res[(size_t)m * N + n0];
                    v1 += res[(size_t)m * N + n0 + 1];
                }
                if (OUTH) {
                    __half2* cp = (__half2*)((__half*)Cv + (size_t)m * N + n0);
                    *cp = __floats2half2_rn(v0, v1);
                } else {
                    float* C = (float*)Cv;
                    if (n0 < N)     C[(size_t)m * N + n0]     = v0;
                    if (n0 + 1 < N) C[(size_t)m * N + n0 + 1] = v1;
                }
            }
        }
    }

    // ---- fused softmax partials (logits GEMM only) ----
    if (STATS) {
        __syncthreads();            // stage buffers dead; reuse smem
        float* smm = (float*)sm;    // [128][NWN]
        float* sms = smm + 128 * NWN;
        #pragma unroll
        for (int f = 0; f < 4; f++) {
            #pragma unroll
            for (int half = 0; half < 2; half++) {
                int rloc = wm * 64 + f * 16 + g + half * 8;
                float mx = -1e30f;
                #pragma unroll
                for (int j = 0; j < 4; j++) {
                    int n0 = bn + wn * 32 + j * 8 + t4 * 2;
                    float v0 = cfr[f][j][half * 2], v1 = cfr[f][j][half * 2 + 1];
                    if (n0 < N)     mx = fmaxf(mx, v0);
                    if (n0 + 1 < N) mx = fmaxf(mx, v1);
                }
                mx = fmaxf(mx, __shfl_xor_sync(0xffffffffu, mx, 1));
                mx = fmaxf(mx, __shfl_xor_sync(0xffffffffu, mx, 2));
                float ss = 0.f;
                #pragma unroll
                for (int j = 0; j < 4; j++) {
                    int n0 = bn + wn * 32 + j * 8 + t4 * 2;
                    float v0 = cfr[f][j][half * 2], v1 = cfr[f][j][half * 2 + 1];
                    if (n0 < N)     ss += __expf(v0 - mx);
                    if (n0 + 1 < N) ss += __expf(v1 - mx);
                }
                ss += __shfl_xor_sync(0xffffffffu, ss, 1);
                ss += __shfl_xor_sync(0xffffffffu, ss, 2);
                if (t4 == 0) { smm[rloc * NWN + wn] = mx; sms[rloc * NWN + wn] = ss; }
            }
        }
        __syncthreads();
        if (tid < 128) {
            float m = -1e30f, s = 0.f;
            #pragma unroll
            for (int w = 0; w < NWN; w++) {
                float m2 = smm[tid * NWN + w], s2 = sms[tid * NWN + w];
                float nm = fmaxf(m, m2);
                s = s * __expf(m - nm) + s2 * __expf(m2 - nm);
                m = nm;
            }
            size_t o = (size_t)(bm + tid) * nblk + blockIdx.y;
            stm[o] = m; sts[o] = s;
        }
    }
}

// ---------------- tensor-core causal flash attention ----------------
// 128 queries / block, 256 threads (8 warps x 16 q-rows). 64-key tiles,
// double-buffered cp.async. Longest q-tiles first (reversed blockIdx.x).
__global__ __launch_bounds__(256)
void attn_mma(const __half* __restrict__ qkv, __half* __restrict__ y) {
    const int qt = gridDim.x - 1 - blockIdx.x;
    const int bh = blockIdx.y;
    const int b = bh / NH, h = bh - b * NH;
    const int tid = threadIdx.x, wid = tid >> 5, lid = tid & 31;
    const int g = lid >> 2, t4 = lid & 3;

    __shared__ __align__(16) __half sQ[128][72];
    __shared__ __align__(16) __half sK[2][64][72];
    __shared__ __align__(16) __half sV[2][64][72];

    const __half* base = qkv + (size_t)b * TT * E3;
    const int q0 = qt * 128;

    {
        int row = tid >> 1;
        int seg = (tid & 1) * 32;
        const __half* qp = base + (size_t)(q0 + row) * E3 + h * HDD + seg;
        __half2 hs = __half2half2(__float2half(0.125f));
        #pragma unroll
        for (int j = 0; j < 4; j++) {
            uint4 v = *(const uint4*)(qp + j * 8);
            __half2* pv = (__half2*)&v;
            #pragma unroll
            for (int k = 0; k < 4; k++) pv[k] = __hmul2(pv[k], hs);
            *(uint4*)&sQ[row][seg + j * 8] = v;
        }
    }

    auto loadKV = [&](int kt, int buf) {
        int r = tid >> 2;
        int cb = (tid & 3) * 2;
        const __half* kp = base + (size_t)(kt * 64 + r) * E3 + ED + h * HDD;
        uint32_t skr = smem_u32(&sK[buf][r][0]);
        uint32_t svr = smem_u32(&sV[buf][r][0]);
        #pragma unroll
        for (int c = 0; c < 2; c++) {
            CP16(skr + (cb + c) * 16, kp + (cb + c) * 8);
            CP16(svr + (cb + c) * 16, kp + ED + (cb + c) * 8);
        }
    };

    loadKV(0, 0); CP_COMMIT();
    __syncthreads();

    uint32_t qf[4][4];
    {
        int qr = wid * 16 + (lid & 15);
        int qc = 8 * (lid >> 4);
        #pragma unroll
        for (int kd = 0; kd < 4; kd++)
            ldsm4(qf[kd], smem_u32(&sQ[qr][kd * 16 + qc]));
    }

    float S[8][4], O[8][4];
    #pragma unroll
    for (int nt = 0; nt < 8; nt++)
        #pragma unroll
        for (int c = 0; c < 4; c++) O[nt][c] = 0.f;
    float m_lo = -1e30f, m_hi = -1e30f, l_lo = 0.f, l_hi = 0.f;

    const int lrow = (lid & 15);
    const int lcol = 8 * (lid >> 4);
    const int qi_lo = q0 + wid * 16 + g;
    const int ktmax = 2 * qt + 1;

    for (int kt = 0; kt <= ktmax; kt++) {
        if (kt < ktmax) { loadKV(kt + 1, (kt + 1) & 1); CP_COMMIT(); CP_WAIT(1); }
        else CP_WAIT(0);
        __syncthreads();
        int buf = kt & 1;

        #pragma unroll
        for (int nt = 0; nt < 8; nt++)
            #pragma unroll
            for (int c = 0; c < 4; c++) S[nt][c] = 0.f;
        #pragma unroll
        for (int kc = 0; kc < 4; kc++) {
            #pragma unroll
            for (int kd = 0; kd < 4; kd++) {
                uint32_t kf[4];
                ldsm4(kf, smem_u32(&sK[buf][kc * 16 + lrow][kd * 16 + lcol]));
                mma_f16(S[kc * 2],     qf[kd], kf[0], kf[2]);
                mma_f16(S[kc * 2 + 1], qf[kd], kf[1], kf[3]);
            }
        }

        if (kt >= 2 * qt) {
            int base_col = kt * 64;
            #pragma unroll
            for (int nt = 0; nt < 8; nt++) {
                int col = base_col + nt * 8 + 2 * t4;
                if (col     > qi_lo)     S[nt][0] = -1e30f;
                if (col + 1 > qi_lo)     S[nt][1] = -1e30f;
                if (col     > qi_lo + 8) S[nt][2] = -1e30f;
                if (col + 1 > qi_lo + 8) S[nt][3] = -1e30f;
            }
        }

        float mx0 = -1e30f, mx1 = -1e30f;
        #pragma unroll
        for (int nt = 0; nt < 8; nt++) {
            mx0 = fmaxf(mx0, fmaxf(S[nt][0], S[nt][1]));
            mx1 = fmaxf(mx1, fmaxf(S[nt][2], S[nt][3]));
        }
        mx0 = fmaxf(mx0, __shfl_xor_sync(0xffffffffu, mx0, 1));
        mx0 = fmaxf(mx0, __shfl_xor_sync(0xffffffffu, mx0, 2));
        mx1 = fmaxf(mx1, __shfl_xor_sync(0xffffffffu, mx1, 1));
        mx1 = fmaxf(mx1, __shfl_xor_sync(0xffffffffu, mx1, 2));
        float mn0 = fmaxf(m_lo, mx0), mn1 = fmaxf(m_hi, mx1);
        float cr0 = __expf(m_lo - mn0), cr1 = __expf(m_hi - mn1);
        float rs0 = 0.f, rs1 = 0.f;
        #pragma unroll
        for (int nt = 0; nt < 8; nt++) {
            S[nt][0] = __expf(S[nt][0] - mn0);
            S[nt][1] = __expf(S[nt][1] - mn0);
            S[nt][2] = __expf(S[nt][2] - mn1);
            S[nt][3] = __expf(S[nt][3] - mn1);
            rs0 += S[nt][0] + S[nt][1];
            rs1 += S[nt][2] + S[nt][3];
        }
        rs0 += __shfl_xor_sync(0xffffffffu, rs0, 1);
        rs0 += __shfl_xor_sync(0xffffffffu, rs0, 2);
        rs1 += __shfl_xor_sync(0xffffffffu, rs1, 1);
        rs1 += __shfl_xor_sync(0xffffffffu, rs1, 2);
        l_lo = l_lo * cr0 + rs0;
        l_hi = l_hi * cr1 + rs1;
        #pragma unroll
        for (int nt = 0; nt < 8; nt++) {
            O[nt][0] *= cr0; O[nt][1] *= cr0;
            O[nt][2] *= cr1; O[nt][3] *= cr1;
        }
        m_lo = mn0; m_hi = mn1;

        #pragma unroll
        for (int kc = 0; kc < 4; kc++) {
            uint32_t pa[4];
            pa[0] = packh2(S[kc * 2][0],     S[kc * 2][1]);
            pa[1] = packh2(S[kc * 2][2],     S[kc * 2][3]);
            pa[2] = packh2(S[kc * 2 + 1][0], S[kc * 2 + 1][1]);
            pa[3] = packh2(S[kc * 2 + 1][2], S[kc * 2 + 1][3]);
            #pragma unroll
            for (int dp = 0; dp < 4; dp++) {
                uint32_t vf[4];
                ldsm4t(vf, smem_u32(&sV[buf][kc * 16 + lrow][dp * 16 + lcol]));
                mma_f16(O[dp * 2],     pa, vf[0], vf[1]);
                mma_f16(O[dp * 2 + 1], pa, vf[2], vf[3]);
            }
        }
        __syncthreads();
    }

    float il0 = 1.f / l_lo, il1 = 1.f / l_hi;
    int tok_lo = b * TT + q0 + wid * 16 + g;
    __half* yl = y + (size_t)tok_lo * ED + h * HDD;
    __half* yh = yl + (size_t)8 * ED;
    #pragma unroll
    for (int nt = 0; nt < 8; nt++) {
        int c = nt * 8 + 2 * t4;
        *(__half2*)(yl + c) = __floats2half2_rn(O[nt][0] * il0, O[nt][1] * il0);
        *(__half2*)(yh + c) = __floats2half2_rn(O[nt][2] * il1, O[nt][3] * il1);
    }
}

// ---------------- NLL finalize from fused partials ----------------
__global__ void nll_fin(const float* __restrict__ stm, const float* __restrict__ sts,
                        const float* __restrict__ logits, const int* __restrict__ tgt,
                        float* __restrict__ nll, int nblk) {
    int row = blockIdx.x;
    int t = threadIdx.x;   // 128
    float m = -1e30f, s = 0.f;
    for (int i = t; i < nblk; i += 128) {
        float m2 = stm[(size_t)row * nblk + i], s2 = sts[(size_t)row * nblk + i];
        float nm = fmaxf(m, m2);
        s = s * __expf(m - nm) + s2 * __expf(m2 - nm);
        m = nm;
    }
    __shared__ float rm[128], rs[128];
    rm[t] = m; rs[t] = s;
    __syncthreads();
    for (int st = 64; st > 0; st >>= 1) {
        if (t < st) {
            float m2 = rm[t + st], s2 = rs[t + st];
            float m1 = rm[t],      s1 = rs[t];
            float nm = fmaxf(m1, m2);
            rm[t] = nm;
            rs[t] = s1 * __expf(m1 - nm) + s2 * __expf(m2 - nm);
        }
        __syncthreads();
    }
    if (t == 0)
        nll[row] = -(logits[(size_t)row * VV + tgt[row]] - rm[0] - logf(rs[0]));
}

__global__ void loss_k(const float* __restrict__ nll, float* __restrict__ out) {
    int t = threadIdx.x;
    __shared__ float red[256];
    float s = 0.f;
    for (int i = t; i < NTOK; i += 256) s += nll[i];
    red[t] = s; __syncthreads();
    for (int st = 128; st > 0; st >>= 1) {
        if (t < st) red[t] += red[t + st];
        __syncthreads();
    }
    if (t == 0) out[0] = red[0] * (1.0f / NTOK);
}

// ---------------- launch ----------------
extern "C" void kernel_launch(void* const* d_in, const int* in_sizes, int n_in,
                              void* d_out, int out_size) {
    const int*   idx    = (const int*)  d_in[0];
    const int*   tgt    = (const int*)  d_in[1];
    const float* wte    = (const float*)d_in[2];
    const float* wpe    = (const float*)d_in[3];
    const float* ln1_g  = (const float*)d_in[4];
    const float* ln1_b  = (const float*)d_in[5];
    const float* attn_w = (const float*)d_in[6];
    const float* attn_b = (const float*)d_in[7];
    const float* proj_w = (const float*)d_in[8];
    const float* proj_b = (const float*)d_in[9];
    const float* ln2_g  = (const float*)d_in[10];
    const float* ln2_b  = (const float*)d_in[11];
    const float* fc1_w  = (const float*)d_in[12];
    const float* fc1_b  = (const float*)d_in[13];
    const float* fc2_w  = (const float*)d_in[14];
    const float* fc2_b  = (const float*)d_in[15];
    const float* lnf_g  = (const float*)d_in[16];
    const float* lnf_b  = (const float*)d_in[17];

    float *x, *nll, *lscratch, *stm, *sts;
    __half *h, *qkv, *y, *ff, *attn_wT, *proj_wT, *fc1_wT, *fc2_wT, *wte_h;
    cudaGetSymbolAddress((void**)&x,   g_x);
    cudaGetSymbolAddress((void**)&h,   g_h);
    cudaGetSymbolAddress((void**)&qkv, g_qkv);
    cudaGetSymbolAddress((void**)&y,   g_y);
    cudaGetSymbolAddress((void**)&ff,  g_ff);
    cudaGetSymbolAddress((void**)&nll, g_nll);
    cudaGetSymbolAddress((void**)&stm, g_stat_m);
    cudaGetSymbolAddress((void**)&sts, g_stat_s);
    cudaGetSymbolAddress((void**)&lscratch, g_logits_scratch);
    cudaGetSymbolAddress((void**)&attn_wT, g_attn_wT);
    cudaGetSymbolAddress((void**)&proj_wT, g_proj_wT);
    cudaGetSymbolAddress((void**)&fc1_wT,  g_fc1_wT);
    cudaGetSymbolAddress((void**)&fc2_wT,  g_fc2_wT);
    cudaGetSymbolAddress((void**)&wte_h,   g_wte_h);

    const int SMB4 = NST * (128 + 128) * RSH * 2;   // 110592 B (NWN=4)
    const int SMB8 = NST * (128 + 256) * RSH * 2;   // 165888 B (NWN=8)
    cudaFuncSetAttribute(gemm_h<4, true,  false, false, true,  false>, cudaFuncAttributeMaxDynamicSharedMemorySize, SMB4);
    cudaFuncSetAttribute(gemm_h<4, true,  false, true,  false, false>, cudaFuncAttributeMaxDynamicSharedMemorySize, SMB4);
    cudaFuncSetAttribute(gemm_h<4, true,  true,  false, true,  false>, cudaFuncAttributeMaxDynamicSharedMemorySize, SMB4);
    cudaFuncSetAttribute(gemm_h<8, false, false, false, false, true >, cudaFuncAttributeMaxDynamicSharedMemorySize, SMB8);

    float* out = (float*)d_out;
    const size_t LOG = (size_t)NTOK * VV;
    float* logits;
    float* lossp;
    if ((size_t)out_size >= LOG + 1) { logits = out; lossp = out + LOG; }
    else if ((size_t)out_size == LOG) { logits = out; lossp = nullptr; }
    else { logits = lscratch; lossp = out; }

    // fused weight prep: all transposes + wte cvt in one launch
    prep_k<<<T_ALL + CVT_BLKS, 256>>>(attn_w, proj_w, fc1_w, fc2_w, wte,
                                      attn_wT, proj_wT, fc1_wT, fc2_wT, wte_h);

    embed_k<<<(NTOK * ED + 255) / 256, 256>>>(idx, wte, wpe, x);

    for (int l = 0; l < NL; l++) {
        ln_k<<<NTOK, 256>>>(x, ln1_g + (size_t)l * ED, ln1_b + (size_t)l * ED, h);

        gemm_h<4, true, false, false, true, false><<<dim3(NTOK / 128, E3 / 128), 256, SMB4>>>(
            NTOK, E3, ED, h, attn_wT + (size_t)l * E3 * ED,
            attn_b + (size_t)l * E3, nullptr, qkv, nullptr, nullptr, 0);

        attn_mma<<<dim3(TT / 128, BB * NH), 256>>>(qkv, y);

        gemm_h<4, true, false, true, false, false><<<dim3(NTOK / 128, ED / 128), 256, SMB4>>>(
            NTOK, ED, ED, y, proj_wT + (size_t)l * ED * ED,
            proj_b + (size_t)l * ED, x, x, nullptr, nullptr, 0);

        ln_k<<<NTOK, 256>>>(x, ln2_g + (size_t)l * ED, ln2_b + (size_t)l * ED, h);

        gemm_h<4, true, true, false, true, false><<<dim3(NTOK / 128, FFD / 128), 256, SMB4>>>(
            NTOK, FFD, ED, h, fc1_wT + (size_t)l * FFD * ED,
            fc1_b + (size_t)l * FFD, nullptr, ff, nullptr, nullptr, 0);

        gemm_h<4, true, false, true, false, false><<<dim3(NTOK / 128, ED / 128), 256, SMB4>>>(
            NTOK, ED, FFD, ff, fc2_wT + (size_t)l * ED * FFD,
            fc2_b + (size_t)l * ED, x, x, nullptr, nullptr, 0);
    }

    ln_k<<<NTOK, 256>>>(x, lnf_g, lnf_b, h);

    // tied lm_head (128x256 blocks, 512 threads) with fused softmax partials
    gemm_h<8, false, false, false, false, true><<<dim3(NTOK / 128, NBLK_LOG), 512, SMB8>>>(
        NTOK, VV, ED, h, wte_h, nullptr, nullptr, logits, stm, sts, NBLK_LOG);

    if (lossp) {
        nll_fin<<<NTOK, 128>>>(stm, sts, logits, tgt, nll, NBLK_LOG);
        loss_k<<<1, 256>>>(nll, lossp);
    }
}

// round 16
// speedup vs baseline: 1.1024x; 1.1024x over previous
#include <cuda_runtime.h>
#include <cuda_fp16.h>
#include <math.h>
#include <stdint.h>

// ---------------- problem constants ----------------
#define BB   2
#define TT   2048
#define NL   2
#define NH   12
#define ED   768
#define HDD  64
#define FFD  3072
#define VV   50257
#define NTOK (BB*TT)      // 4096
#define E3   (3*ED)       // 2304
#define NBLK ((VV + 127) / 128)   // 393 logits column-blocks

// ---------------- scratch (device globals: allocation-free) ----------------
__device__ float  g_x   [NTOK*ED];          // fp32 residual stream
__device__ __half g_h   [NTOK*ED];          // LN output (GEMM A input)
__device__ __half g_qkv [NTOK*E3];
__device__ __half g_y   [NTOK*ED];
__device__ __half g_ff  [NTOK*FFD];
__device__ float  g_nll [NTOK];
__device__ float  g_stat_m[(size_t)NTOK*NBLK];
__device__ float  g_stat_s[(size_t)NTOK*NBLK];
__device__ float  g_logits_scratch[(size_t)NTOK*VV];
// fp16 transposed weights Bt[N,K] + fp16 wte
__device__ __half g_attn_wT[NL*E3*ED];
__device__ __half g_proj_wT[NL*ED*ED];
__device__ __half g_fc1_wT [NL*FFD*ED];
__device__ __half g_fc2_wT [NL*ED*FFD];
__device__ __half g_wte_h  [(size_t)VV*ED];

// ---------------- helpers ----------------
__device__ __forceinline__ uint32_t smem_u32(const void* p) {
    uint32_t a;
    asm("{ .reg .u64 t; cvta.to.shared.u64 t, %1; cvt.u32.u64 %0, t; }" : "=r"(a) : "l"(p));
    return a;
}
#define CP16(sm, gp) \
    asm volatile("cp.async.cg.shared.global [%0], [%1], 16;" :: "r"(sm), "l"(gp) : "memory")
#define CP16Z(sm, gp) \
    asm volatile("cp.async.ca.shared.global [%0], [%1], 16, 0;" :: "r"(sm), "l"(gp) : "memory")
#define CP_COMMIT() asm volatile("cp.async.commit_group;" ::: "memory")
#define CP_WAIT(n)  asm volatile("cp.async.wait_group %0;" :: "n"(n) : "memory")

__device__ __forceinline__ void ldsm4(uint32_t r[4], uint32_t addr) {
    asm volatile("ldmatrix.sync.aligned.m8n8.x4.shared.b16 {%0,%1,%2,%3}, [%4];"
                 : "=r"(r[0]), "=r"(r[1]), "=r"(r[2]), "=r"(r[3]) : "r"(addr));
}
__device__ __forceinline__ void ldsm4t(uint32_t r[4], uint32_t addr) {
    asm volatile("ldmatrix.sync.aligned.m8n8.x4.trans.shared.b16 {%0,%1,%2,%3}, [%4];"
                 : "=r"(r[0]), "=r"(r[1]), "=r"(r[2]), "=r"(r[3]) : "r"(addr));
}
__device__ __forceinline__ void mma_f16(float c[4], const uint32_t a[4],
                                        uint32_t b0, uint32_t b1) {
    asm volatile("mma.sync.aligned.m16n8k16.row.col.f32.f16.f16.f32 "
                 "{%0,%1,%2,%3}, {%4,%5,%6,%7}, {%8,%9}, {%0,%1,%2,%3};"
                 : "+f"(c[0]), "+f"(c[1]), "+f"(c[2]), "+f"(c[3])
                 : "r"(a[0]), "r"(a[1]), "r"(a[2]), "r"(a[3]), "r"(b0), "r"(b1));
}
__device__ __forceinline__ uint32_t packh2(float x, float y) {
    __half2 h = __floats2half2_rn(x, y);
    return *(uint32_t*)&h;
}

// ---------------- layernorm (fp32 in -> fp16 out) ----------------
__global__ void ln_k(const float* __restrict__ x, const float* __restrict__ g,
                     const float* __restrict__ b, __half* __restrict__ o) {
    int row = blockIdx.x;
    int t = threadIdx.x;
    const float* xr = x + (size_t)row * ED;
    float v0 = xr[t], v1 = xr[t + 256], v2 = xr[t + 512];
    float s1 = v0 + v1 + v2;
    float s2 = v0 * v0 + v1 * v1 + v2 * v2;
    __shared__ float r1[256], r2[256];
    r1[t] = s1; r2[t] = s2;
    __syncthreads();
    for (int s = 128; s > 0; s >>= 1) {
        if (t < s) { r1[t] += r1[t + s]; r2[t] += r2[t + s]; }
        __syncthreads();
    }
    float mu  = r1[0] * (1.0f / ED);
    float var = r2[0] * (1.0f / ED) - mu * mu;
    float inv = rsqrtf(var + 1e-5f);
    __half* orow = o + (size_t)row * ED;
    orow[t]       = __float2half((v0 - mu) * inv * g[t]       + b[t]);
    orow[t + 256] = __float2half((v1 - mu) * inv * g[t + 256] + b[t + 256]);
    orow[t + 512] = __float2half((v2 - mu) * inv * g[t + 512] + b[t + 512]);
}

// ---------------- fused prep: 8 transposes + wte cvt + embedding, ONE launch ----------------
#define T_ATTN 1728
#define T_PROJ 576
#define T_FC1  2304
#define T_FC2  2304
#define T_LAYER (T_ATTN + T_PROJ + T_FC1 + T_FC2)   // 6912
#define T_ALL   (NL * T_LAYER)                      // 13824
#define WTE_EL  ((size_t)VV * ED)                   // 38597376
#define CVT_PB  2048
#define CVT_BLKS ((int)((WTE_EL + CVT_PB - 1) / CVT_PB))
#define EMB_BLKS ((NTOK * ED) / 256)                // 12288

__device__ __forceinline__ void tr_tile(const float* __restrict__ in, __half* __restrict__ out,
                                        int K, int N, int tk, int tn,
                                        int tx, int ty, float (*t)[33]) {
    int n0 = tn * 32, k0 = tk * 32;
    #pragma unroll
    for (int i = ty; i < 32; i += 8)
        t[i][tx] = in[(size_t)(k0 + i) * N + n0 + tx];
    __syncthreads();
    #pragma unroll
    for (int i = ty; i < 32; i += 8)
        out[(size_t)(n0 + i) * K + k0 + tx] = __float2half(t[tx][i]);
}

__global__ __launch_bounds__(256)
void prep_k(const float* __restrict__ attn_w, const float* __restrict__ proj_w,
            const float* __restrict__ fc1_w,  const float* __restrict__ fc2_w,
            const float* __restrict__ wte,    const float* __restrict__ wpe,
            const int* __restrict__ idx,
            __half* __restrict__ attn_wT, __half* __restrict__ proj_wT,
            __half* __restrict__ fc1_wT,  __half* __restrict__ fc2_wT,
            __half* __restrict__ wte_h,   float* __restrict__ x) {
    int b = blockIdx.x;
    if (b < T_ALL) {
        __shared__ float t[32][33];
        int tx = threadIdx.x & 31, ty = threadIdx.x >> 5;
        int layer = b / T_LAYER;
        int r = b - layer * T_LAYER;
        if (r < T_ATTN) {
            tr_tile(attn_w + (size_t)layer * ED * E3, attn_wT + (size_t)layer * E3 * ED,
                    ED, E3, r / (E3 / 32), r % (E3 / 32), tx, ty, t);
        } else if ((r -= T_ATTN) < T_PROJ) {
            tr_tile(proj_w + (size_t)layer * ED * ED, proj_wT + (size_t)layer * ED * ED,
                    ED, ED, r / (ED / 32), r % (ED / 32), tx, ty, t);
        } else if ((r -= T_PROJ) < T_FC1) {
            tr_tile(fc1_w + (size_t)layer * ED * FFD, fc1_wT + (size_t)layer * FFD * ED,
                    ED, FFD, r / (FFD / 32), r % (FFD / 32), tx, ty, t);
        } else {
            r -= T_FC1;
            tr_tile(fc2_w + (size_t)layer * FFD * ED, fc2_wT + (size_t)layer * ED * FFD,
                    FFD, ED, r / (ED / 32), r % (ED / 32), tx, ty, t);
        }
    } else if (b < T_ALL + CVT_BLKS) {
        size_t base = (size_t)(b - T_ALL) * CVT_PB + (size_t)threadIdx.x * 8;
        if (base + 8 <= WTE_EL) {
            float4 v0 = *(const float4*)(wte + base);
            float4 v1 = *(const float4*)(wte + base + 4);
            __half2 h0 = __floats2half2_rn(v0.x, v0.y);
            __half2 h1 = __floats2half2_rn(v0.z, v0.w);
            __half2 h2 = __floats2half2_rn(v1.x, v1.y);
            __half2 h3 = __floats2half2_rn(v1.z, v1.w);
            uint2 o0 = make_uint2(*(uint32_t*)&h0, *(uint32_t*)&h1);
            uint2 o1 = make_uint2(*(uint32_t*)&h2, *(uint32_t*)&h3);
            *(uint2*)(wte_h + base)     = o0;
            *(uint2*)(wte_h + base + 4) = o1;
        } else {
            for (size_t i = base; i < WTE_EL; i++)
                wte_h[i] = __float2half(wte[i]);
        }
    } else {
        // embedding: x = wte[idx] + wpe
        int i = (b - T_ALL - CVT_BLKS) * 256 + threadIdx.x;
        int tok = i / ED, e = i - tok * ED;
        int t = tok % TT;
        x[i] = wte[(size_t)idx[tok] * ED + e] + wpe[(size_t)t * ED + e];
    }
}

// ---------------- fp16 mma.sync GEMM: C[M,N] = A[M,K] @ Bt[N,K]^T ----------------
// 128x128 block tile, BK=64, 256 threads = 8 warps (2M x 4N), warp tile 64x32.
// 3-stage cp.async pipeline (prefetch distance 2 = 128 K-elems), one sync/iter.
#define RSH    72
#define TILE_B (128 * RSH * 2)      // 18432 B per matrix tile
#define STG_B  (2 * TILE_B)         // 36864 B per stage
#define NST    3

// STATS: also emit per-(row, col-block) softmax partials (max, sum-exp) for NLL fusion.
template<bool BIAS, bool GELU, bool RES, bool OUTH, bool STATS>
__global__ __launch_bounds__(256)
void gemm_h(int M, int N, int K,
            const __half* __restrict__ A, const __half* __restrict__ B,
            const float* __restrict__ bias, const float* __restrict__ res,
            void* __restrict__ Cv,
            float* __restrict__ stm, float* __restrict__ sts, int nblk) {
    extern __shared__ char sm[];
    uint32_t sbase = smem_u32(sm);

    int tid = threadIdx.x;
    int wid = tid >> 5;
    int lid = tid & 31;
    int g = lid >> 2;          // 0..7
    int t4 = lid & 3;          // 0..3
    int wm = wid & 1;          // M warp (0..1) -> 64 rows
    int wn = wid >> 1;         // N warp (0..3) -> 32 cols
    int bm = blockIdx.x * 128;
    int bn = blockIdx.y * 128;

    int mat = lid >> 3, r8 = lid & 7;
    int a_row  = wm * 64 + ((mat & 1) << 3) + r8;
    int a_colb = ((mat >> 1) << 3) * 2;
    int b_row  = wn * 32 + ((mat >> 1) << 3) + r8;
    int b_colb = ((mat & 1) << 3) * 2;

    float cfr[4][4][4];
    #pragma unroll
    for (int f = 0; f < 4; f++)
        #pragma unroll
        for (int j = 0; j < 4; j++)
            #pragma unroll
            for (int c = 0; c < 4; c++) cfr[f][j][c] = 0.f;

    const int KT = K >> 6;     // 64-K tiles

    auto load_tile = [&](int kt, int stage) {
        int k0 = kt << 6;
        uint32_t st = sbase + (uint32_t)stage * STG_B;
        #pragma unroll
        for (int i = 0; i < 4; i++) {
            int lin = i * 256 + tid;
            int r = lin >> 3;          // 0..127
            int c = lin & 7;           // 16B chunk (8 per 128B row)
            const __half* gpa = A + (size_t)(bm + r) * K + k0 + c * 8;
            CP16(st + (uint32_t)r * (RSH * 2) + (uint32_t)c * 16, gpa);
            int n = bn + r;
            uint32_t smb = st + (uint32_t)TILE_B + (uint32_t)r * (RSH * 2) + (uint32_t)c * 16;
            const __half* gpb = B + (size_t)n * K + k0 + c * 8;
            if (n < N) CP16(smb, gpb);
            else       CP16Z(smb, B);
        }
    };

    auto compute = [&](int stage) {
        uint32_t stA = sbase + (uint32_t)stage * STG_B;
        uint32_t aBase = stA + (uint32_t)a_row * (RSH * 2) + (uint32_t)a_colb;
        uint32_t bBase = stA + TILE_B + (uint32_t)b_row * (RSH * 2) + (uint32_t)b_colb;
        #pragma unroll
        for (int s = 0; s < 4; s++) {
            uint32_t a[4][4], b[2][4];
            #pragma unroll
            for (int f = 0; f < 4; f++)
                ldsm4(a[f], aBase + s * 32 + f * (16 * RSH * 2));
            #pragma unroll
            for (int p = 0; p < 2; p++)
                ldsm4(b[p], bBase + s * 32 + p * (16 * RSH * 2));
            #pragma unroll
            for (int f = 0; f < 4; f++)
                #pragma unroll
                for (int j = 0; j < 4; j++)
                    mma_f16(cfr[f][j], a[f], b[j >> 1][(j & 1) * 2], b[j >> 1][(j & 1) * 2 + 1]);
        }
    };

    // one-sync-per-iteration 3-stage pipeline, prefetch distance 2 (x64 K).
    load_tile(0, 0); CP_COMMIT();
    if (KT > 1) { load_tile(1, 1); CP_COMMIT(); }
    for (int kt = 0; kt < KT; kt++) {
        if (kt + 1 < KT) CP_WAIT(1);
        else             CP_WAIT(0);
        __syncthreads();
        if (kt + 2 < KT) { load_tile(kt + 2, (kt + 2) % NST); CP_COMMIT(); }
        compute(kt % NST);
    }

    // ---- write C (scalar fp32 stores: N may be odd -> no STG.64) ----
    #pragma unroll
    for (int f = 0; f < 4; f++) {
        #pragma unroll
        for (int j = 0; j < 4; j++) {
            int m0 = bm + wm * 64 + f * 16 + g;
            int n0 = bn + wn * 32 + j * 8 + t4 * 2;
            #pragma unroll
            for (int half = 0; half < 2; half++) {
                int m = m0 + half * 8;
                float v0 = cfr[f][j][half * 2];
                float v1 = cfr[f][j][half * 2 + 1];
                if (BIAS) { v0 += bias[n0]; v1 += bias[n0 + 1]; }
                if (GELU) {
                    v0 = 0.5f * v0 * (1.f + erff(v0 * 0.70710678118654752f));
                    v1 = 0.5f * v1 * (1.f + erff(v1 * 0.70710678118654752f));
                }
                if (RES) {
                    v0 += res[(size_t)m * N + n0];
                    v1 += res[(size_t)m * N + n0 + 1];
                }
                if (OUTH) {
                    __half2* cp = (__half2*)((__half*)Cv + (size_t)m * N + n0);
                    *cp = __floats2half2_rn(v0, v1);
                } else {
                    float* C = (float*)Cv;
                    if (n0 < N)     C[(size_t)m * N + n0]     = v0;
                    if (n0 + 1 < N) C[(size_t)m * N + n0 + 1] = v1;
                }
            }
        }
    }

    // ---- fused softmax partials (logits GEMM only) ----
    if (STATS) {
        __syncthreads();            // stage buffers dead; reuse smem
        float* smm = (float*)sm;    // [128][4]
        float* sms = smm + 512;
        #pragma unroll
        for (int f = 0; f < 4; f++) {
            #pragma unroll
            for (int half = 0; half < 2; half++) {
                int rloc = wm * 64 + f * 16 + g + half * 8;
                float mx = -1e30f;
                #pragma unroll
                for (int j = 0; j < 4; j++) {
                    int n0 = bn + wn * 32 + j * 8 + t4 * 2;
                    float v0 = cfr[f][j][half * 2], v1 = cfr[f][j][half * 2 + 1];
                    if (n0 < N)     mx = fmaxf(mx, v0);
                    if (n0 + 1 < N) mx = fmaxf(mx, v1);
                }
                mx = fmaxf(mx, __shfl_xor_sync(0xffffffffu, mx, 1));
                mx = fmaxf(mx, __shfl_xor_sync(0xffffffffu, mx, 2));
                float ss = 0.f;
                #pragma unroll
                for (int j = 0; j < 4; j++) {
                    int n0 = bn + wn * 32 + j * 8 + t4 * 2;
                    float v0 = cfr[f][j][half * 2], v1 = cfr[f][j][half * 2 + 1];
                    if (n0 < N)     ss += __expf(v0 - mx);
                    if (n0 + 1 < N) ss += __expf(v1 - mx);
                }
                ss += __shfl_xor_sync(0xffffffffu, ss, 1);
                ss += __shfl_xor_sync(0xffffffffu, ss, 2);
                if (t4 == 0) { smm[rloc * 4 + wn] = mx; sms[rloc * 4 + wn] = ss; }
            }
        }
        __syncthreads();
        if (tid < 128) {
            float m = -1e30f, s = 0.f;
            #pragma unroll
            for (int w = 0; w < 4; w++) {
                float m2 = smm[tid * 4 + w], s2 = sms[tid * 4 + w];
                float nm = fmaxf(m, m2);
                s = s * __expf(m - nm) + s2 * __expf(m2 - nm);
                m = nm;
            }
            size_t o = (size_t)(bm + tid) * nblk + blockIdx.y;
            stm[o] = m; sts[o] = s;
        }
    }
}

// ---------------- tensor-core causal flash attention ----------------
// 128 queries / block, 256 threads (8 warps x 16 q-rows). 64-key tiles,
// double-buffered cp.async. Longest q-tiles first (reversed blockIdx.x).
__global__ __launch_bounds__(256)
void attn_mma(const __half* __restrict__ qkv, __half* __restrict__ y) {
    const int qt = gridDim.x - 1 - blockIdx.x;
    const int bh = blockIdx.y;
    const int b = bh / NH, h = bh - b * NH;
    const int tid = threadIdx.x, wid = tid >> 5, lid = tid & 31;
    const int g = lid >> 2, t4 = lid & 3;

    __shared__ __align__(16) __half sQ[128][72];
    __shared__ __align__(16) __half sK[2][64][72];
    __shared__ __align__(16) __half sV[2][64][72];

    const __half* base = qkv + (size_t)b * TT * E3;
    const int q0 = qt * 128;

    {
        int row = tid >> 1;
        int seg = (tid & 1) * 32;
        const __half* qp = base + (size_t)(q0 + row) * E3 + h * HDD + seg;
        __half2 hs = __half2half2(__float2half(0.125f));
        #pragma unroll
        for (int j = 0; j < 4; j++) {
            uint4 v = *(const uint4*)(qp + j * 8);
            __half2* pv = (__half2*)&v;
            #pragma unroll
            for (int k = 0; k < 4; k++) pv[k] = __hmul2(pv[k], hs);
            *(uint4*)&sQ[row][seg + j * 8] = v;
        }
    }

    auto loadKV = [&](int kt, int buf) {
        int r = tid >> 2;
        int cb = (tid & 3) * 2;
        const __half* kp = base + (size_t)(kt * 64 + r) * E3 + ED + h * HDD;
        uint32_t skr = smem_u32(&sK[buf][r][0]);
        uint32_t svr = smem_u32(&sV[buf][r][0]);
        #pragma unroll
        for (int c = 0; c < 2; c++) {
            CP16(skr + (cb + c) * 16, kp + (cb + c) * 8);
            CP16(svr + (cb + c) * 16, kp + ED + (cb + c) * 8);
        }
    };

    loadKV(0, 0); CP_COMMIT();
    __syncthreads();

    uint32_t qf[4][4];
    {
        int qr = wid * 16 + (lid & 15);
        int qc = 8 * (lid >> 4);
        #pragma unroll
        for (int kd = 0; kd < 4; kd++)
            ldsm4(qf[kd], smem_u32(&sQ[qr][kd * 16 + qc]));
    }

    float S[8][4], O[8][4];
    #pragma unroll
    for (int nt = 0; nt < 8; nt++)
        #pragma unroll
        for (int c = 0; c < 4; c++) O[nt][c] = 0.f;
    float m_lo = -1e30f, m_hi = -1e30f, l_lo = 0.f, l_hi = 0.f;

    const int lrow = (lid & 15);
    const int lcol = 8 * (lid >> 4);
    const int qi_lo = q0 + wid * 16 + g;
    const int ktmax = 2 * qt + 1;

    for (int kt = 0; kt <= ktmax; kt++) {
        if (kt < ktmax) { loadKV(kt + 1, (kt + 1) & 1); CP_COMMIT(); CP_WAIT(1); }
        else CP_WAIT(0);
        __syncthreads();
        int buf = kt & 1;

        #pragma unroll
        for (int nt = 0; nt < 8; nt++)
            #pragma unroll
            for (int c = 0; c < 4; c++) S[nt][c] = 0.f;
        #pragma unroll
        for (int kc = 0; kc < 4; kc++) {
            #pragma unroll
            for (int kd = 0; kd < 4; kd++) {
                uint32_t kf[4];
                ldsm4(kf, smem_u32(&sK[buf][kc * 16 + lrow][kd * 16 + lcol]));
                mma_f16(S[kc * 2],     qf[kd], kf[0], kf[2]);
                mma_f16(S[kc * 2 + 1], qf[kd], kf[1], kf[3]);
            }
        }

        if (kt >= 2 * qt) {
            int base_col = kt * 64;
            #pragma unroll
            for (int nt = 0; nt < 8; nt++) {
                int col = base_col + nt * 8 + 2 * t4;
                if (col     > qi_lo)     S[nt][0] = -1e30f;
                if (col + 1 > qi_lo)     S[nt][1] = -1e30f;
                if (col     > qi_lo + 8) S[nt][2] = -1e30f;
                if (col + 1 > qi_lo + 8) S[nt][3] = -1e30f;
            }
        }

        float mx0 = -1e30f, mx1 = -1e30f;
        #pragma unroll
        for (int nt = 0; nt < 8; nt++) {
            mx0 = fmaxf(mx0, fmaxf(S[nt][0], S[nt][1]));
            mx1 = fmaxf(mx1, fmaxf(S[nt][2], S[nt][3]));
        }
        mx0 = fmaxf(mx0, __shfl_xor_sync(0xffffffffu, mx0, 1));
        mx0 = fmaxf(mx0, __shfl_xor_sync(0xffffffffu, mx0, 2));
        mx1 = fmaxf(mx1, __shfl_xor_sync(0xffffffffu, mx1, 1));
        mx1 = fmaxf(mx1, __shfl_xor_sync(0xffffffffu, mx1, 2));
        float mn0 = fmaxf(m_lo, mx0), mn1 = fmaxf(m_hi, mx1);
        float cr0 = __expf(m_lo - mn0), cr1 = __expf(m_hi - mn1);
        float rs0 = 0.f, rs1 = 0.f;
        #pragma unroll
        for (int nt = 0; nt < 8; nt++) {
            S[nt][0] = __expf(S[nt][0] - mn0);
            S[nt][1] = __expf(S[nt][1] - mn0);
            S[nt][2] = __expf(S[nt][2] - mn1);
            S[nt][3] = __expf(S[nt][3] - mn1);
            rs0 += S[nt][0] + S[nt][1];
            rs1 += S[nt][2] + S[nt][3];
        }
        rs0 += __shfl_xor_sync(0xffffffffu, rs0, 1);
        rs0 += __shfl_xor_sync(0xffffffffu, rs0, 2);
        rs1 += __shfl_xor_sync(0xffffffffu, rs1, 1);
        rs1 += __shfl_xor_sync(0xffffffffu, rs1, 2);
        l_lo = l_lo * cr0 + rs0;
        l_hi = l_hi * cr1 + rs1;
        #pragma unroll
        for (int nt = 0; nt < 8; nt++) {
            O[nt][0] *= cr0; O[nt][1] *= cr0;
            O[nt][2] *= cr1; O[nt][3] *= cr1;
        }
        m_lo = mn0; m_hi = mn1;

        #pragma unroll
        for (int kc = 0; kc < 4; kc++) {
            uint32_t pa[4];
            pa[0] = packh2(S[kc * 2][0],     S[kc * 2][1]);
            pa[1] = packh2(S[kc * 2][2],     S[kc * 2][3]);
            pa[2] = packh2(S[kc * 2 + 1][0], S[kc * 2 + 1][1]);
            pa[3] = packh2(S[kc * 2 + 1][2], S[kc * 2 + 1][3]);
            #pragma unroll
            for (int dp = 0; dp < 4; dp++) {
                uint32_t vf[4];
                ldsm4t(vf, smem_u32(&sV[buf][kc * 16 + lrow][dp * 16 + lcol]));
                mma_f16(O[dp * 2],     pa, vf[0], vf[1]);
                mma_f16(O[dp * 2 + 1], pa, vf[2], vf[3]);
            }
        }
        __syncthreads();
    }

    float il0 = 1.f / l_lo, il1 = 1.f / l_hi;
    int tok_lo = b * TT + q0 + wid * 16 + g;
    __half* yl = y + (size_t)tok_lo * ED + h * HDD;
    __half* yh = yl + (size_t)8 * ED;
    #pragma unroll
    for (int nt = 0; nt < 8; nt++) {
        int c = nt * 8 + 2 * t4;
        *(__half2*)(yl + c) = __floats2half2_rn(O[nt][0] * il0, O[nt][1] * il0);
        *(__half2*)(yh + c) = __floats2half2_rn(O[nt][2] * il1, O[nt][3] * il1);
    }
}

// ---------------- NLL finalize from fused partials ----------------
__global__ void nll_fin(const float* __restrict__ stm, const float* __restrict__ sts,
                        const float* __restrict__ logits, const int* __restrict__ tgt,
                        float* __restrict__ nll) {
    int row = blockIdx.x;
    int t = threadIdx.x;   // 128
    float m = -1e30f, s = 0.f;
    for (int i = t; i < NBLK; i += 128) {
        float m2 = stm[(size_t)row * NBLK + i], s2 = sts[(size_t)row * NBLK + i];
        float nm = fmaxf(m, m2);
        s = s * __expf(m - nm) + s2 * __expf(m2 - nm);
        m = nm;
    }
    __shared__ float rm[128], rs[128];
    rm[t] = m; rs[t] = s;
    __syncthreads();
    for (int st = 64; st > 0; st >>= 1) {
        if (t < st) {
            float m2 = rm[t + st], s2 = rs[t + st];
            float m1 = rm[t],      s1 = rs[t];
            float nm = fmaxf(m1, m2);
            rm[t] = nm;
            rs[t] = s1 * __expf(m1 - nm) + s2 * __expf(m2 - nm);
        }
        __syncthreads();
    }
    if (t == 0)
        nll[row] = -(logits[(size_t)row * VV + tgt[row]] - rm[0] - logf(rs[0]));
}

__global__ void loss_k(const float* __restrict__ nll, float* __restrict__ out) {
    int t = threadIdx.x;
    __shared__ float red[256];
    float s = 0.f;
    for (int i = t; i < NTOK; i += 256) s += nll[i];
    red[t] = s; __syncthreads();
    for (int st = 128; st > 0; st >>= 1) {
        if (t < st) red[t] += red[t + st];
        __syncthreads();
    }
    if (t == 0) out[0] = red[0] * (1.0f / NTOK);
}

// ---------------- launch ----------------
extern "C" void kernel_launch(void* const* d_in, const int* in_sizes, int n_in,
                              void* d_out, int out_size) {
    const int*   idx    = (const int*)  d_in[0];
    const int*   tgt    = (const int*)  d_in[1];
    const float* wte    = (const float*)d_in[2];
    const float* wpe    = (const float*)d_in[3];
    const float* ln1_g  = (const float*)d_in[4];
    const float* ln1_b  = (const float*)d_in[5];
    const float* attn_w = (const float*)d_in[6];
    const float* attn_b = (const float*)d_in[7];
    const float* proj_w = (const float*)d_in[8];
    const float* proj_b = (const float*)d_in[9];
    const float* ln2_g  = (const float*)d_in[10];
    const float* ln2_b  = (const float*)d_in[11];
    const float* fc1_w  = (const float*)d_in[12];
    const float* fc1_b  = (const float*)d_in[13];
    const float* fc2_w  = (const float*)d_in[14];
    const float* fc2_b  = (const float*)d_in[15];
    const float* lnf_g  = (const float*)d_in[16];
    const float* lnf_b  = (const float*)d_in[17];

    float *x, *nll, *lscratch, *stm, *sts;
    __half *h, *qkv, *y, *ff, *attn_wT, *proj_wT, *fc1_wT, *fc2_wT, *wte_h;
    cudaGetSymbolAddress((void**)&x,   g_x);
    cudaGetSymbolAddress((void**)&h,   g_h);
    cudaGetSymbolAddress((void**)&qkv, g_qkv);
    cudaGetSymbolAddress((void**)&y,   g_y);
    cudaGetSymbolAddress((void**)&ff,  g_ff);
    cudaGetSymbolAddress((void**)&nll, g_nll);
    cudaGetSymbolAddress((void**)&stm, g_stat_m);
    cudaGetSymbolAddress((void**)&sts, g_stat_s);
    cudaGetSymbolAddress((void**)&lscratch, g_logits_scratch);
    cudaGetSymbolAddress((void**)&attn_wT, g_attn_wT);
    cudaGetSymbolAddress((void**)&proj_wT, g_proj_wT);
    cudaGetSymbolAddress((void**)&fc1_wT,  g_fc1_wT);
    cudaGetSymbolAddress((void**)&fc2_wT,  g_fc2_wT);
    cudaGetSymbolAddress((void**)&wte_h,   g_wte_h);

    const int SMB = NST * STG_B;   // 110592 bytes (3 stages x BK=64)
    cudaFuncSetAttribute(gemm_h<true,  false, false, true,  false>, cudaFuncAttributeMaxDynamicSharedMemorySize, SMB);
    cudaFuncSetAttribute(gemm_h<true,  false, true,  false, false>, cudaFuncAttributeMaxDynamicSharedMemorySize, SMB);
    cudaFuncSetAttribute(gemm_h<true,  true,  false, true,  false>, cudaFuncAttributeMaxDynamicSharedMemorySize, SMB);
    cudaFuncSetAttribute(gemm_h<false, false, false, false, true >, cudaFuncAttributeMaxDynamicSharedMemorySize, SMB);

    float* out = (float*)d_out;
    const size_t LOG = (size_t)NTOK * VV;
    float* logits;
    float* lossp;
    if ((size_t)out_size >= LOG + 1) { logits = out; lossp = out + LOG; }
    else if ((size_t)out_size == LOG) { logits = out; lossp = nullptr; }
    else { logits = lscratch; lossp = out; }

    // fused prep: all transposes + wte cvt + embedding in one launch
    prep_k<<<T_ALL + CVT_BLKS + EMB_BLKS, 256>>>(
        attn_w, proj_w, fc1_w, fc2_w, wte, wpe, idx,
        attn_wT, proj_wT, fc1_wT, fc2_wT, wte_h, x);

    for (int l = 0; l < NL; l++) {
        ln_k<<<NTOK, 256>>>(x, ln1_g + (size_t)l * ED, ln1_b + (size_t)l * ED, h);

        gemm_h<true, false, false, true, false><<<dim3(NTOK / 128, E3 / 128), 256, SMB>>>(
            NTOK, E3, ED, h, attn_wT + (size_t)l * E3 * ED,
            attn_b + (size_t)l * E3, nullptr, qkv, nullptr, nullptr, 0);

        attn_mma<<<dim3(TT / 128, BB * NH), 256>>>(qkv, y);

        gemm_h<true, false, true, false, false><<<dim3(NTOK / 128, ED / 128), 256, SMB>>>(
            NTOK, ED, ED, y, proj_wT + (size_t)l * ED * ED,
            proj_b + (size_t)l * ED, x, x, nullptr, nullptr, 0);

        ln_k<<<NTOK, 256>>>(x, ln2_g + (size_t)l * ED, ln2_b + (size_t)l * ED, h);

        gemm_h<true, true, false, true, false><<<dim3(NTOK / 128, FFD / 128), 256, SMB>>>(
            NTOK, FFD, ED, h, fc1_wT + (size_t)l * FFD * ED,
            fc1_b + (size_t)l * FFD, nullptr, ff, nullptr, nullptr, 0);

        gemm_h<true, false, true, false, false><<<dim3(NTOK / 128, ED / 128), 256, SMB>>>(
            NTOK, ED, FFD, ff, fc2_wT + (size_t)l * ED * FFD,
            fc2_b + (size_t)l * ED, x, x, nullptr, nullptr, 0);
    }

    ln_k<<<NTOK, 256>>>(x, lnf_g, lnf_b, h);

    // tied lm_head with fused softmax partials (proven 128x128 / 256-thread shape)
    gemm_h<false, false, false, false, true><<<dim3(NTOK / 128, NBLK), 256, SMB>>>(
        NTOK, VV, ED, h, wte_h, nullptr, nullptr, logits, stm, sts, NBLK);

    if (lossp) {
        nll_fin<<<NTOK, 128>>>(stm, sts, logits, tgt, nll);
        loss_k<<<1, 256>>>(nll, lossp);
    }
}